// round 10
// baseline (speedup 1.0000x reference)
#include <cuda_runtime.h>
#include <cstdint>

// RealEmbedding: out[bt, i*C_OUT + j] = x[bt, i] * W[i, j] + b[i, j]
// B=64, T=512, C_IN=128, C_OUT=16 -> rows = 32768, row_out = 2048 floats (8KB).
//
// R9: move the 256MB store stream off the LSU (STG.128 issue cost = 12 cyc was
// co-binding with DRAM). Compute into a 3-buffer smem ring (STS.128), then one
// elected thread per CTA issues cp.async.bulk (shared -> global) per 2-row tile.

static constexpr int C_IN    = 128;
static constexpr int C_OUT   = 16;
static constexpr int ROW_OUT = C_IN * C_OUT;        // 2048 floats = 8192 bytes
static constexpr int TPB     = 512;                 // one float4 lane per (i, j4)
static constexpr int RPT     = 2;                   // rows per tile
static constexpr int NBUF    = 3;                   // 3 x 16KB = 48KB static smem
static constexpr int TILE_F4 = RPT * ROW_OUT / 4;   // 1024 float4 per buffer

__device__ __forceinline__ uint32_t smem_u32(const void* p) {
    uint32_t a;
    asm("{ .reg .u64 t; cvta.to.shared.u64 t, %1; cvt.u32.u64 %0, t; }"
        : "=r"(a) : "l"(p));
    return a;
}

__global__ __launch_bounds__(TPB, 4)
void real_embedding_kernel(const float* __restrict__ x,
                           const float* __restrict__ W,
                           const float* __restrict__ Bv,
                           float* __restrict__ out,
                           int n_rows, int rows_per_cta)
{
    __shared__ float4 sbuf[NBUF][TILE_F4];          // 49152 bytes

    const int tid = threadIdx.x;                    // 0..511
    const int i   = tid >> 2;                       // input channel 0..127
    const int j4  = tid & 3;                        // output quad 0..3

    // Per-thread constants (slot within a row == tid, since out_off/4 = i*4+j4).
    const float4 w4 = __ldg(reinterpret_cast<const float4*>(W  + i * C_OUT + j4 * 4));
    const float4 b4 = __ldg(reinterpret_cast<const float4*>(Bv + i * C_OUT + j4 * 4));

    const int row_begin = blockIdx.x * rows_per_cta;
    int row_end = row_begin + rows_per_cta;
    if (row_end > n_rows) row_end = n_rows;

    int s = 0;                                      // ring buffer slot
    for (int r = row_begin; r < row_end; r += RPT) {
        const int nr = (row_end - r >= RPT) ? RPT : (row_end - r);

        // Backpressure: at most 2 bulk-store groups in flight -> buffer s free.
        if (tid == 0)
            asm volatile("cp.async.bulk.wait_group.read 2;" ::: "memory");
        __syncthreads();

        // Compute nr rows into smem (independent LDGs issued up front).
        float xv[RPT];
        #pragma unroll
        for (int k = 0; k < RPT; k++)
            if (k < nr) xv[k] = __ldcs(x + (size_t)(r + k) * C_IN + i);

        #pragma unroll
        for (int k = 0; k < RPT; k++) {
            if (k < nr) {
                float4 o;
                o.x = fmaf(xv[k], w4.x, b4.x);
                o.y = fmaf(xv[k], w4.y, b4.y);
                o.z = fmaf(xv[k], w4.z, b4.z);
                o.w = fmaf(xv[k], w4.w, b4.w);
                sbuf[s][k * (ROW_OUT / 4) + tid] = o;   // STS.128, conflict-free
            }
        }
        __syncthreads();

        // One thread issues the bulk store (16KB, or 8KB on the tail).
        if (tid == 0) {
            asm volatile("fence.proxy.async.shared::cta;" ::: "memory");
            const uint32_t src   = smem_u32(&sbuf[s][0]);
            float*         dst   = out + (size_t)r * ROW_OUT;
            const uint32_t bytes = (uint32_t)nr * (ROW_OUT * 4);
            asm volatile(
                "cp.async.bulk.global.shared::cta.bulk_group [%0], [%1], %2;\n\t"
                "cp.async.bulk.commit_group;"
                :: "l"(dst), "r"(src), "r"(bytes) : "memory");
        }

        s = (s + 1 == NBUF) ? 0 : s + 1;
    }

    // Drain: don't exit with bulk stores pending.
    if (tid == 0)
        asm volatile("cp.async.bulk.wait_group.read 0;" ::: "memory");
}

extern "C" void kernel_launch(void* const* d_in, const int* in_sizes, int n_in,
                              void* d_out, int out_size)
{
    const float* x  = (const float*)d_in[0];   // [B*T*C_IN]
    const float* W  = (const float*)d_in[1];   // [C_IN*C_OUT]
    const float* Bv = (const float*)d_in[2];   // [C_IN*C_OUT]
    float* out = (float*)d_out;

    const int n_rows = in_sizes[0] / C_IN;     // 32768

    // 4 CTAs/SM x 148 SMs = 592 CTAs; contiguous row chunks (even, for full tiles).
    int blocks = 592;
    int max_blocks = (n_rows + RPT - 1) / RPT;
    if (blocks > max_blocks) blocks = max_blocks;
    int rows_per_cta = (n_rows + blocks - 1) / blocks;
    rows_per_cta = (rows_per_cta + RPT - 1) / RPT * RPT;   // multiple of RPT

    real_embedding_kernel<<<blocks, TPB>>>(x, W, Bv, out, n_rows, rows_per_cta);
}